// round 1
// baseline (speedup 1.0000x reference)
#include <cuda_runtime.h>
#include <math.h>

// Problem constants
#define S_LEN 3136
#define E_DIM 1024
#define H_NUM 16
#define D_DIM 64

// Scratch (device globals; allocation is forbidden)
__device__ float g_q[H_NUM * S_LEN * D_DIM];
__device__ float g_k[H_NUM * S_LEN * D_DIM];
__device__ float g_v[H_NUM * S_LEN * D_DIM];
__device__ float g_ao[S_LEN * E_DIM];

// ---------------------------------------------------------------------------
// Tiled SGEMM: C = alpha * A * op(B)
//   A: [M,K] row-major, lda
//   TRANSB=true : B [N,K] row-major (C = A B^T)
//   TRANSB=false: B [K,N] row-major (C = A B)
//   HEADC=true  : C written head-major: C[((n>>6)*headS + m)*64 + (n&63)]
//   HEADC=false : C[m*ldc + n]
// Tiles: BM=BN=64, BK=16, 256 threads, 4x4 per thread.
// Requires M%64==0, N%64==0, K%16==0 (true for all launches here).
// ---------------------------------------------------------------------------
template <bool TRANSB, bool HEADC>
__global__ void gemm64_kernel(const float* __restrict__ A,
                              const float* __restrict__ B,
                              float* __restrict__ C,
                              int M, int N, int K,
                              int lda, int ldb, int ldc,
                              long sA, long sB, long sC,
                              float alpha, int headS) {
    A += (long)blockIdx.z * sA;
    B += (long)blockIdx.z * sB;
    C += (long)blockIdx.z * sC;

    const int mBase = blockIdx.y * 64;
    const int nBase = blockIdx.x * 64;

    __shared__ float As[16][64];
    __shared__ float Bs[16][64];

    const int t  = threadIdx.x;      // 0..255
    const int tx = t & 15;
    const int ty = t >> 4;

    float acc[4][4];
#pragma unroll
    for (int i = 0; i < 4; i++)
#pragma unroll
        for (int j = 0; j < 4; j++) acc[i][j] = 0.0f;

    for (int k0 = 0; k0 < K; k0 += 16) {
        // Load A tile: 64 rows x 16 k, float4 per thread
        {
            const int row = t >> 2;
            const int kc  = (t & 3) * 4;
            float4 v = *(const float4*)(A + (long)(mBase + row) * lda + k0 + kc);
            As[kc + 0][row] = v.x;
            As[kc + 1][row] = v.y;
            As[kc + 2][row] = v.z;
            As[kc + 3][row] = v.w;
        }
        // Load B tile
        if (TRANSB) {
            const int row = t >> 2;           // n index 0..63
            const int kc  = (t & 3) * 4;
            float4 v = *(const float4*)(B + (long)(nBase + row) * ldb + k0 + kc);
            Bs[kc + 0][row] = v.x;
            Bs[kc + 1][row] = v.y;
            Bs[kc + 2][row] = v.z;
            Bs[kc + 3][row] = v.w;
        } else {
            const int kr = t >> 4;            // k index 0..15
            const int nc = (t & 15) * 4;
            float4 v = *(const float4*)(B + (long)(k0 + kr) * ldb + nBase + nc);
            Bs[kr][nc + 0] = v.x;
            Bs[kr][nc + 1] = v.y;
            Bs[kr][nc + 2] = v.z;
            Bs[kr][nc + 3] = v.w;
        }
        __syncthreads();

#pragma unroll
        for (int k = 0; k < 16; k++) {
            float a[4], b[4];
#pragma unroll
            for (int i = 0; i < 4; i++) a[i] = As[k][ty * 4 + i];
#pragma unroll
            for (int j = 0; j < 4; j++) b[j] = Bs[k][tx * 4 + j];
#pragma unroll
            for (int i = 0; i < 4; i++)
#pragma unroll
                for (int j = 0; j < 4; j++) acc[i][j] = fmaf(a[i], b[j], acc[i][j]);
        }
        __syncthreads();
    }

#pragma unroll
    for (int i = 0; i < 4; i++) {
        const int m = mBase + ty * 4 + i;
#pragma unroll
        for (int j = 0; j < 4; j++) {
            const int n = nBase + tx * 4 + j;
            const float v = acc[i][j] * alpha;
            if (HEADC) {
                // head-major: [h][m][d], h = n>>6, d = n&63
                C[(((long)(n >> 6) * headS + m) << 6) + (n & 63)] = v;
            } else {
                C[(long)m * ldc + n] = v;
            }
        }
    }
}

// ---------------------------------------------------------------------------
// RoPE applied in-place to g_q and g_k (head-major [H][S][64]).
// One thread per (h, s, d<32) pair.
// ---------------------------------------------------------------------------
__global__ void rope_kernel(float* __restrict__ Q, float* __restrict__ K,
                            const float* __restrict__ cosp,
                            const float* __restrict__ sinp) {
    const long total = (long)H_NUM * S_LEN * 32;
    long idx = (long)blockIdx.x * blockDim.x + threadIdx.x;
    if (idx >= total) return;
    const int d = (int)(idx & 31);
    const long hs = idx >> 5;            // h*S + s
    const int s = (int)(hs % S_LEN);
    const long base = hs << 6;           // *64

    const float c1 = cosp[s * 64 + d];
    const float s1 = sinp[s * 64 + d];
    const float c2 = cosp[s * 64 + d + 32];
    const float s2 = sinp[s * 64 + d + 32];

    float q1 = Q[base + d], q2 = Q[base + d + 32];
    Q[base + d]      = q1 * c1 - q2 * s1;
    Q[base + d + 32] = q2 * c2 + q1 * s2;

    float k1 = K[base + d], k2 = K[base + d + 32];
    K[base + d]      = k1 * c1 - k2 * s1;
    K[base + d + 32] = k2 * c2 + k1 * s2;
}

// ---------------------------------------------------------------------------
// Row softmax, in-place. One block per row; row cached in smem (3136 floats).
// ---------------------------------------------------------------------------
__global__ void softmax_kernel(float* __restrict__ W) {
    __shared__ float buf[S_LEN];
    __shared__ float red[256];
    const long row = blockIdx.x;
    float* p = W + row * (long)S_LEN;
    const int t = threadIdx.x;

    float m = -INFINITY;
    for (int i = t; i < S_LEN; i += 256) {
        float v = p[i];
        buf[i] = v;
        m = fmaxf(m, v);
    }
    red[t] = m;
    __syncthreads();
#pragma unroll
    for (int s = 128; s > 0; s >>= 1) {
        if (t < s) red[t] = fmaxf(red[t], red[t + s]);
        __syncthreads();
    }
    m = red[0];
    __syncthreads();

    float sum = 0.0f;
    for (int i = t; i < S_LEN; i += 256) {
        float e = __expf(buf[i] - m);
        buf[i] = e;
        sum += e;
    }
    red[t] = sum;
    __syncthreads();
#pragma unroll
    for (int s = 128; s > 0; s >>= 1) {
        if (t < s) red[t] += red[t + s];
        __syncthreads();
    }
    const float inv = 1.0f / red[0];

    for (int i = t; i < S_LEN; i += 256) p[i] = buf[i] * inv;
}

// ---------------------------------------------------------------------------
// Launch
// ---------------------------------------------------------------------------
extern "C" void kernel_launch(void* const* d_in, const int* in_sizes, int n_in,
                              void* d_out, int out_size) {
    const float* hidden = (const float*)d_in[0];  // [S,E]
    const float* cosp   = (const float*)d_in[1];  // [S,64]
    const float* sinp   = (const float*)d_in[2];  // [S,64]
    const float* wq     = (const float*)d_in[3];  // [E,E]
    const float* wk     = (const float*)d_in[4];
    const float* wv     = (const float*)d_in[5];
    const float* wo     = (const float*)d_in[6];

    float* out    = (float*)d_out;                       // attn_output [S,E]
    float* attn_w = out + (long)S_LEN * E_DIM;           // attn_weights [H,S,S]

    float* qg;  cudaGetSymbolAddress((void**)&qg, g_q);
    float* kg;  cudaGetSymbolAddress((void**)&kg, g_k);
    float* vg;  cudaGetSymbolAddress((void**)&vg, g_v);
    float* aog; cudaGetSymbolAddress((void**)&aog, g_ao);

    const float scale = 0.125f;  // 1/sqrt(64)

    // 1) Q/K/V projections: [S,E] x [E,E]^T -> head-major [H][S][64]
    dim3 gProj(E_DIM / 64, S_LEN / 64, 1);
    gemm64_kernel<true, true><<<gProj, 256>>>(hidden, wq, qg,
        S_LEN, E_DIM, E_DIM, E_DIM, E_DIM, 0, 0, 0, 0, 1.0f, S_LEN);
    gemm64_kernel<true, true><<<gProj, 256>>>(hidden, wk, kg,
        S_LEN, E_DIM, E_DIM, E_DIM, E_DIM, 0, 0, 0, 0, 1.0f, S_LEN);
    gemm64_kernel<true, true><<<gProj, 256>>>(hidden, wv, vg,
        S_LEN, E_DIM, E_DIM, E_DIM, E_DIM, 0, 0, 0, 0, 1.0f, S_LEN);

    // 2) RoPE on Q and K
    {
        const long total = (long)H_NUM * S_LEN * 32;
        const int tpb = 256;
        const int blocks = (int)((total + tpb - 1) / tpb);
        rope_kernel<<<blocks, tpb>>>(qg, kg, cosp, sinp);
    }

    // 3) scores = scale * Q K^T per head -> attn_w [H][S][S]
    dim3 gScore(S_LEN / 64, S_LEN / 64, H_NUM);
    gemm64_kernel<true, false><<<gScore, 256>>>(qg, kg, attn_w,
        S_LEN, S_LEN, D_DIM, D_DIM, D_DIM, S_LEN,
        (long)S_LEN * D_DIM, (long)S_LEN * D_DIM, (long)S_LEN * S_LEN,
        scale, 0);

    // 4) softmax rows (in place, H*S rows)
    softmax_kernel<<<H_NUM * S_LEN, 256>>>(attn_w);

    // 5) attn_out_h = P V per head -> g_ao [S][E] (heads interleaved back)
    dim3 gPV(1, S_LEN / 64, H_NUM);
    gemm64_kernel<false, false><<<gPV, 256>>>(attn_w, vg, aog,
        S_LEN, D_DIM, S_LEN, S_LEN, D_DIM, E_DIM,
        (long)S_LEN * S_LEN, (long)S_LEN * D_DIM, (long)D_DIM,
        1.0f, 0);

    // 6) attn_output = AO Wo^T -> d_out[0 : S*E]
    dim3 gOut(E_DIM / 64, S_LEN / 64, 1);
    gemm64_kernel<true, false><<<gOut, 256>>>(aog, wo, out,
        S_LEN, E_DIM, E_DIM, E_DIM, E_DIM, E_DIM, 0, 0, 0, 1.0f, 0);
}

// round 3
// speedup vs baseline: 2.0807x; 2.0807x over previous
#include <cuda_runtime.h>
#include <cuda_bf16.h>
#include <math.h>
#include <stdint.h>

#define S_LEN 3136
#define E_DIM 1024
#define H_NUM 16
#define D_DIM 64

typedef __nv_bfloat16 bf16;

// ---------------------------------------------------------------------------
// Device scratch (allocation is forbidden)
// ---------------------------------------------------------------------------
__device__ float g_q[H_NUM * S_LEN * D_DIM];
__device__ float g_k[H_NUM * S_LEN * D_DIM];
__device__ float g_v[H_NUM * S_LEN * D_DIM];

__device__ __align__(16) bf16 g_Hhi[S_LEN * E_DIM];
__device__ __align__(16) bf16 g_Hlo[S_LEN * E_DIM];
__device__ __align__(16) bf16 g_Whi[4][E_DIM * E_DIM];
__device__ __align__(16) bf16 g_Wlo[4][E_DIM * E_DIM];
__device__ __align__(16) bf16 g_Qhi[H_NUM * S_LEN * D_DIM];
__device__ __align__(16) bf16 g_Qlo[H_NUM * S_LEN * D_DIM];
__device__ __align__(16) bf16 g_Khi[H_NUM * S_LEN * D_DIM];
__device__ __align__(16) bf16 g_Klo[H_NUM * S_LEN * D_DIM];
__device__ __align__(16) bf16 g_Vthi[H_NUM * D_DIM * S_LEN];   // [h][d][s]
__device__ __align__(16) bf16 g_Vtlo[H_NUM * D_DIM * S_LEN];
__device__ __align__(16) bf16 g_Phi[(long)H_NUM * S_LEN * S_LEN];
__device__ __align__(16) bf16 g_Plo[(long)H_NUM * S_LEN * S_LEN];
__device__ __align__(16) bf16 g_AOhi[S_LEN * E_DIM];
__device__ __align__(16) bf16 g_AOlo[S_LEN * E_DIM];

// ---------------------------------------------------------------------------
// PTX helpers (sm_80-era: cp.async + ldmatrix + mma.sync — valid on sm_103)
// ---------------------------------------------------------------------------
__device__ __forceinline__ uint32_t smem_u32(const void* p) {
    uint32_t a;
    asm("{ .reg .u64 t; cvta.to.shared.u64 t, %1; cvt.u32.u64 %0, t; }" : "=r"(a) : "l"(p));
    return a;
}

__device__ __forceinline__ void cp16(uint32_t dst, const void* src, int srcsize) {
    asm volatile("cp.async.cg.shared.global [%0], [%1], 16, %2;"
                 :: "r"(dst), "l"(src), "r"(srcsize));
}
__device__ __forceinline__ void cpcommit() { asm volatile("cp.async.commit_group;"); }
template <int N> __device__ __forceinline__ void cpwait() {
    asm volatile("cp.async.wait_group %0;" :: "n"(N));
}

__device__ __forceinline__ void ldm4(uint32_t* r, uint32_t a) {
    asm volatile("ldmatrix.sync.aligned.m8n8.x4.shared.b16 {%0,%1,%2,%3}, [%4];"
                 : "=r"(r[0]), "=r"(r[1]), "=r"(r[2]), "=r"(r[3]) : "r"(a));
}
__device__ __forceinline__ void ldm2(uint32_t* r, uint32_t a) {
    asm volatile("ldmatrix.sync.aligned.m8n8.x2.shared.b16 {%0,%1}, [%2];"
                 : "=r"(r[0]), "=r"(r[1]) : "r"(a));
}
__device__ __forceinline__ void mma16816(float* d, const uint32_t* a, const uint32_t* b) {
    asm volatile("mma.sync.aligned.m16n8k16.row.col.f32.bf16.bf16.f32 "
                 "{%0,%1,%2,%3}, {%4,%5,%6,%7}, {%8,%9}, {%0,%1,%2,%3};"
                 : "+f"(d[0]), "+f"(d[1]), "+f"(d[2]), "+f"(d[3])
                 : "r"(a[0]), "r"(a[1]), "r"(a[2]), "r"(a[3]), "r"(b[0]), "r"(b[1]));
}

// ---------------------------------------------------------------------------
// bf16x3 TN GEMM via mma.sync: C[M=128 tile, N_TILE] = A x B^T
//   A: bf16 hi/lo rows [M, K-contig], row stride aRow (elements)
//   B: bf16 hi/lo rows [N, K-contig], row stride bRow
// EPI 0: fp32 C[z*cBatch + m*ldc + n]
// EPI 1: head-major fp32 C[((n>>6)*S + m)*64 + (n&63)]
// EPI 2: bf16 split Dhi/Dlo[m*E + z*64 + n]
// ---------------------------------------------------------------------------
template <int N_TILE, int EPI>
__global__ void __launch_bounds__(256, 1) mma_gemm(
    const bf16* __restrict__ Ahi, const bf16* __restrict__ Alo, long aRow, long aBatch,
    const bf16* __restrict__ Bhi, const bf16* __restrict__ Blo, long bRow, long bBatch,
    float* __restrict__ C, long ldc, long cBatch,
    bf16* __restrict__ Dhi, bf16* __restrict__ Dlo,
    int kChunks, int M_valid, int N_valid) {

    constexpr int AST = 80;                 // smem bytes per 32-bf16 row (64 + 16 pad)
    constexpr int A_BYTES = 128 * AST;
    constexpr int B_BYTES = N_TILE * AST;
    constexpr int STAGE = 2 * A_BYTES + 2 * B_BYTES;

    extern __shared__ char smem[];
    const uint32_t sb = smem_u32(smem);

    const int tid = threadIdx.x;
    const int wid = tid >> 5, lane = tid & 31;
    constexpr int WC = (N_TILE == 128) ? 4 : 2;          // warp cols
    constexpr int WM = (N_TILE == 128) ? 64 : 32;        // warp m-tile
    constexpr int WN = 32;                               // warp n-tile
    constexpr int MI = WM / 16, NI = WN / 8;
    const int warpM = (wid / WC) * WM;
    const int warpN = (wid % WC) * WN;

    const int mBase = blockIdx.y * 128;
    const int nBase = blockIdx.x * N_TILE;
    const int z = blockIdx.z;
    Ahi += aBatch * z; Alo += aBatch * z;
    Bhi += bBatch * z; Blo += bBatch * z;

    float acc[MI][NI][4];
#pragma unroll
    for (int i = 0; i < MI; i++)
#pragma unroll
        for (int j = 0; j < NI; j++)
#pragma unroll
            for (int q = 0; q < 4; q++) acc[i][j][q] = 0.0f;

    auto issue_loads = [&](int c) {
        const long k0 = (long)c * 32;
        const uint32_t st = sb + (c & 1) * STAGE;
        // A hi/lo: 128 rows x 4 x 16B
        for (int i = tid; i < 512; i += 256) {
            const int r = i >> 2, u = i & 3;
            const int row = mBase + r;
            const int ok = (row < M_valid) ? 16 : 0;
            const long srow = (row < M_valid) ? row : (M_valid - 1);
            const long off = srow * aRow + k0 + u * 8;
            const uint32_t dst = st + r * AST + u * 16;
            cp16(dst, Ahi + off, ok);
            cp16(dst + A_BYTES, Alo + off, ok);
        }
        // B hi/lo: N_TILE rows x 4 x 16B
        for (int i = tid; i < N_TILE * 4; i += 256) {
            const int r = i >> 2, u = i & 3;
            const int row = nBase + r;
            const int ok = (row < N_valid) ? 16 : 0;
            const long srow = (row < N_valid) ? row : (N_valid - 1);
            const long off = srow * bRow + k0 + u * 8;
            const uint32_t dst = st + 2 * A_BYTES + r * AST + u * 16;
            cp16(dst, Bhi + off, ok);
            cp16(dst + B_BYTES, Blo + off, ok);
        }
        cpcommit();
    };

    issue_loads(0);

    for (int c = 0; c < kChunks; c++) {
        if (c + 1 < kChunks) { issue_loads(c + 1); cpwait<1>(); }
        else                 { cpwait<0>(); }
        __syncthreads();

        const uint32_t st = sb + (c & 1) * STAGE;
        const uint32_t aH = st, aL = st + A_BYTES;
        const uint32_t bH = st + 2 * A_BYTES, bL = bH + B_BYTES;

#pragma unroll
        for (int s = 0; s < 2; s++) {
            uint32_t aHf[MI][4], aLf[MI][4], bHf[NI][2], bLf[NI][2];
            const int arow = warpM + (lane & 15);
            const uint32_t acol = s * 32 + (lane >> 4) * 16;
#pragma unroll
            for (int mi = 0; mi < MI; mi++) {
                const uint32_t ao = (uint32_t)((arow + mi * 16) * AST) + acol;
                ldm4(aHf[mi], aH + ao);
                ldm4(aLf[mi], aL + ao);
            }
            const int l16 = lane & 15;
            const int brow = warpN + (l16 & 7);
            const uint32_t bcol = s * 32 + (l16 >> 3) * 16;
#pragma unroll
            for (int ni = 0; ni < NI; ni++) {
                const uint32_t bo = (uint32_t)((brow + ni * 8) * AST) + bcol;
                ldm2(bHf[ni], bH + bo);
                ldm2(bLf[ni], bL + bo);
            }
#pragma unroll
            for (int mi = 0; mi < MI; mi++)
#pragma unroll
                for (int ni = 0; ni < NI; ni++) {
                    mma16816(acc[mi][ni], aHf[mi], bHf[ni]);
                    mma16816(acc[mi][ni], aHf[mi], bLf[ni]);
                    mma16816(acc[mi][ni], aLf[mi], bHf[ni]);
                }
        }
        __syncthreads();
    }

    // epilogue
#pragma unroll
    for (int mi = 0; mi < MI; mi++) {
#pragma unroll
        for (int ni = 0; ni < NI; ni++) {
            const int row0 = mBase + warpM + mi * 16 + (lane >> 2);
            const int col0 = nBase + warpN + ni * 8 + (lane & 3) * 2;
#pragma unroll
            for (int h = 0; h < 2; h++) {
                const int row = row0 + h * 8;
                if (row >= M_valid) continue;
#pragma unroll
                for (int q = 0; q < 2; q++) {
                    const int n = col0 + q;
                    const float v = acc[mi][ni][h * 2 + q];
                    if (EPI == 0) {
                        if (n < N_valid) C[(long)z * cBatch + (long)row * ldc + n] = v;
                    } else if (EPI == 1) {
                        C[(((long)(n >> 6) * S_LEN + row) << 6) + (n & 63)] = v;
                    } else {
                        const long o = (long)row * E_DIM + (long)z * 64 + n;
                        bf16 hi = __float2bfloat16(v);
                        Dhi[o] = hi;
                        Dlo[o] = __float2bfloat16(v - __bfloat162float(hi));
                    }
                }
            }
        }
    }
}

// ---------------------------------------------------------------------------
// Split kernel: fp32 -> (bf16 hi, bf16 lo)
// ---------------------------------------------------------------------------
__global__ void split_kernel(const float* __restrict__ src, bf16* __restrict__ hi,
                             bf16* __restrict__ lo, long n) {
    long i = ((long)blockIdx.x * blockDim.x + threadIdx.x) * 4;
    if (i >= n) return;
    float4 v = *(const float4*)(src + i);
    float f[4] = {v.x, v.y, v.z, v.w};
#pragma unroll
    for (int j = 0; j < 4; j++) {
        bf16 h = __float2bfloat16(f[j]);
        hi[i + j] = h;
        lo[i + j] = __float2bfloat16(f[j] - __bfloat162float(h));
    }
}

// ---------------------------------------------------------------------------
// RoPE + bf16 split of Q (scaled by 1/8) and K (fp32 head-major [h][s][64])
// ---------------------------------------------------------------------------
__global__ void rope_split_kernel(const float* __restrict__ Q, const float* __restrict__ K,
                                  const float* __restrict__ cosp, const float* __restrict__ sinp) {
    const long total = (long)H_NUM * S_LEN * 32;
    long idx = (long)blockIdx.x * blockDim.x + threadIdx.x;
    if (idx >= total) return;
    const int d = (int)(idx & 31);
    const long hs = idx >> 5;
    const int s = (int)(hs % S_LEN);
    const long base = hs << 6;

    const float c1 = cosp[s * 64 + d], s1 = sinp[s * 64 + d];
    const float c2 = cosp[s * 64 + d + 32], s2 = sinp[s * 64 + d + 32];

    float q1 = Q[base + d], q2 = Q[base + d + 32];
    float qa = (q1 * c1 - q2 * s1) * 0.125f;
    float qb = (q2 * c2 + q1 * s2) * 0.125f;
    float k1 = K[base + d], k2 = K[base + d + 32];
    float ka = k1 * c1 - k2 * s1;
    float kb = k2 * c2 + k1 * s2;

    bf16 h;
    h = __float2bfloat16(qa); g_Qhi[base + d] = h; g_Qlo[base + d] = __float2bfloat16(qa - __bfloat162float(h));
    h = __float2bfloat16(qb); g_Qhi[base + d + 32] = h; g_Qlo[base + d + 32] = __float2bfloat16(qb - __bfloat162float(h));
    h = __float2bfloat16(ka); g_Khi[base + d] = h; g_Klo[base + d] = __float2bfloat16(ka - __bfloat162float(h));
    h = __float2bfloat16(kb); g_Khi[base + d + 32] = h; g_Klo[base + d + 32] = __float2bfloat16(kb - __bfloat162float(h));
}

// ---------------------------------------------------------------------------
// V transpose + split: fp32 [h][s][64] -> bf16 [h][d][s] hi/lo
// ---------------------------------------------------------------------------
__global__ void vtrans_kernel(const float* __restrict__ V) {
    __shared__ float tile[64][65];
    const int h = blockIdx.z;
    const int s0 = blockIdx.x * 64;
    const int t = threadIdx.x;
    for (int i = t; i < 4096; i += 256) {
        int s = i >> 6, d = i & 63;
        tile[s][d] = V[((long)h * S_LEN + s0 + s) * 64 + d];
    }
    __syncthreads();
    for (int i = t; i < 4096; i += 256) {
        int d = i >> 6, s = i & 63;
        float v = tile[s][d];
        bf16 hi = __float2bfloat16(v);
        long o = ((long)h * 64 + d) * S_LEN + s0 + s;
        g_Vthi[o] = hi;
        g_Vtlo[o] = __float2bfloat16(v - __bfloat162float(hi));
    }
}

// ---------------------------------------------------------------------------
// Softmax rows in-place (fp32) + emit bf16 hi/lo of normalized P
// ---------------------------------------------------------------------------
__global__ void softmax_split_kernel(float* __restrict__ W) {
    __shared__ float buf[S_LEN];
    __shared__ float red[256];
    const long row = blockIdx.x;
    float* p = W + row * (long)S_LEN;
    bf16* phi = g_Phi + row * (long)S_LEN;
    bf16* plo = g_Plo + row * (long)S_LEN;
    const int t = threadIdx.x;

    float m = -INFINITY;
    for (int i = t; i < S_LEN; i += 256) { float v = p[i]; buf[i] = v; m = fmaxf(m, v); }
    red[t] = m; __syncthreads();
#pragma unroll
    for (int s = 128; s > 0; s >>= 1) { if (t < s) red[t] = fmaxf(red[t], red[t + s]); __syncthreads(); }
    m = red[0]; __syncthreads();

    float sum = 0.f;
    for (int i = t; i < S_LEN; i += 256) { float e = __expf(buf[i] - m); buf[i] = e; sum += e; }
    red[t] = sum; __syncthreads();
#pragma unroll
    for (int s = 128; s > 0; s >>= 1) { if (t < s) red[t] += red[t + s]; __syncthreads(); }
    const float inv = 1.0f / red[0];

    for (int i = t; i < S_LEN; i += 256) {
        float v = buf[i] * inv;
        p[i] = v;
        bf16 hi = __float2bfloat16(v);
        phi[i] = hi;
        plo[i] = __float2bfloat16(v - __bfloat162float(hi));
    }
}

// ---------------------------------------------------------------------------
// Launch
// ---------------------------------------------------------------------------
extern "C" void kernel_launch(void* const* d_in, const int* in_sizes, int n_in,
                              void* d_out, int out_size) {
    const float* hidden = (const float*)d_in[0];
    const float* cosp   = (const float*)d_in[1];
    const float* sinp   = (const float*)d_in[2];
    const float* w[4]   = {(const float*)d_in[3], (const float*)d_in[4],
                           (const float*)d_in[5], (const float*)d_in[6]};

    float* out    = (float*)d_out;
    float* attn_w = out + (long)S_LEN * E_DIM;

    float* qg; cudaGetSymbolAddress((void**)&qg, g_q);
    float* kg; cudaGetSymbolAddress((void**)&kg, g_k);
    float* vg; cudaGetSymbolAddress((void**)&vg, g_v);
    bf16 *Hhi, *Hlo, *Whi, *Wlo, *Qhi, *Qlo, *Khi, *Klo, *Vthi, *Vtlo, *Phi, *Plo, *AOhi, *AOlo;
    cudaGetSymbolAddress((void**)&Hhi, g_Hhi);  cudaGetSymbolAddress((void**)&Hlo, g_Hlo);
    cudaGetSymbolAddress((void**)&Whi, g_Whi);  cudaGetSymbolAddress((void**)&Wlo, g_Wlo);
    cudaGetSymbolAddress((void**)&Qhi, g_Qhi);  cudaGetSymbolAddress((void**)&Qlo, g_Qlo);
    cudaGetSymbolAddress((void**)&Khi, g_Khi);  cudaGetSymbolAddress((void**)&Klo, g_Klo);
    cudaGetSymbolAddress((void**)&Vthi, g_Vthi); cudaGetSymbolAddress((void**)&Vtlo, g_Vtlo);
    cudaGetSymbolAddress((void**)&Phi, g_Phi);  cudaGetSymbolAddress((void**)&Plo, g_Plo);
    cudaGetSymbolAddress((void**)&AOhi, g_AOhi); cudaGetSymbolAddress((void**)&AOlo, g_AOlo);

    const int SMEM128 = 2 * (2 * 128 * 80 + 2 * 128 * 80);  // 81920
    const int SMEM64  = 2 * (2 * 128 * 80 + 2 * 64 * 80);   // 61440
    cudaFuncSetAttribute(mma_gemm<128, 0>, cudaFuncAttributeMaxDynamicSharedMemorySize, SMEM128);
    cudaFuncSetAttribute(mma_gemm<128, 1>, cudaFuncAttributeMaxDynamicSharedMemorySize, SMEM128);
    cudaFuncSetAttribute(mma_gemm<64, 2>,  cudaFuncAttributeMaxDynamicSharedMemorySize, SMEM64);

    // 1) bf16 splits of hidden + weights
    {
        long n = (long)S_LEN * E_DIM;
        split_kernel<<<(int)((n / 4 + 255) / 256), 256>>>(hidden, Hhi, Hlo, n);
        long nw = (long)E_DIM * E_DIM;
        for (int i = 0; i < 4; i++)
            split_kernel<<<(int)((nw / 4 + 255) / 256), 256>>>(w[i], Whi + (long)i * nw, Wlo + (long)i * nw, nw);
    }

    // 2) QKV projections (head-major fp32)
    {
        dim3 g(E_DIM / 128, (S_LEN + 127) / 128, 1);
        long nw = (long)E_DIM * E_DIM;
        mma_gemm<128, 1><<<g, 256, SMEM128>>>(Hhi, Hlo, E_DIM, 0, Whi + 0 * nw, Wlo + 0 * nw, E_DIM, 0,
                                              qg, 0, 0, nullptr, nullptr, 32, S_LEN, E_DIM);
        mma_gemm<128, 1><<<g, 256, SMEM128>>>(Hhi, Hlo, E_DIM, 0, Whi + 1 * nw, Wlo + 1 * nw, E_DIM, 0,
                                              kg, 0, 0, nullptr, nullptr, 32, S_LEN, E_DIM);
        mma_gemm<128, 1><<<g, 256, SMEM128>>>(Hhi, Hlo, E_DIM, 0, Whi + 2 * nw, Wlo + 2 * nw, E_DIM, 0,
                                              vg, 0, 0, nullptr, nullptr, 32, S_LEN, E_DIM);
    }

    // 3) RoPE + split (1/sqrt(D) folded into Q); V transpose + split
    {
        long total = (long)H_NUM * S_LEN * 32;
        rope_split_kernel<<<(int)((total + 255) / 256), 256>>>(qg, kg, cosp, sinp);
        dim3 gv(S_LEN / 64, 1, H_NUM);
        vtrans_kernel<<<gv, 256>>>(vg);
    }

    // 4) scores = (Q*scale) K^T per head -> attn_w fp32
    {
        dim3 g((S_LEN + 127) / 128, (S_LEN + 127) / 128, H_NUM);
        mma_gemm<128, 0><<<g, 256, SMEM128>>>(Qhi, Qlo, 64, (long)S_LEN * 64,
                                              Khi, Klo, 64, (long)S_LEN * 64,
                                              attn_w, S_LEN, (long)S_LEN * S_LEN,
                                              nullptr, nullptr, 2, S_LEN, S_LEN);
    }

    // 5) softmax (writes normalized fp32 + bf16 P splits)
    softmax_split_kernel<<<H_NUM * S_LEN, 256>>>(attn_w);

    // 6) PV -> AO bf16 splits
    {
        dim3 g(1, (S_LEN + 127) / 128, H_NUM);
        mma_gemm<64, 2><<<g, 256, SMEM64>>>(Phi, Plo, S_LEN, (long)S_LEN * S_LEN,
                                            Vthi, Vtlo, S_LEN, (long)64 * S_LEN,
                                            nullptr, 0, 0, AOhi, AOlo, 98, S_LEN, 64);
    }

    // 7) out = AO Wo^T
    {
        dim3 g(E_DIM / 128, (S_LEN + 127) / 128, 1);
        long nw = (long)E_DIM * E_DIM;
        mma_gemm<128, 0><<<g, 256, SMEM128>>>(AOhi, AOlo, E_DIM, 0, Whi + 3 * nw, Wlo + 3 * nw, E_DIM, 0,
                                              out, E_DIM, 0, nullptr, nullptr, 32, S_LEN, E_DIM);
    }
}